// round 8
// baseline (speedup 1.0000x reference)
#include <cuda_runtime.h>
#include <cuda_fp16.h>
#include <math.h>

// ---------------------------------------------------------------------------
// DenseCRF mean-field with permutohedral lattice filtering.
// 21-ch lattice buffers stored as fp16 (24 padded ch = 48B rows = 3 uint4),
// fp32 compute, fp32 1-channel normalization chain, fused update+splat
// (one thread per pixel, FFMA-only exp), merged bi/sp launches,
// triple-buffered with zero riding in blur pass 0.
// ---------------------------------------------------------------------------

#define CC 21
#define GRPH 3                      // uint4 groups per fp16 row (8 halves each)
static constexpr int       NPIX    = 512 * 512;
static constexpr long long ROWS_BI = 6LL * NPIX + 1;
static constexpr long long ROWS_SP = 3LL * NPIX + 1;

// fp16 value buffers (uint4 = 8 halves)
__device__ uint4 g_hb0[ROWS_BI * GRPH];
__device__ uint4 g_hb1[ROWS_BI * GRPH];
__device__ uint4 g_hb2[ROWS_BI * GRPH];
__device__ uint4 g_hs0[ROWS_SP * GRPH];
__device__ uint4 g_hs1[ROWS_SP * GRPH];
__device__ uint4 g_hs2[ROWS_SP * GRPH];
// fp32 1-channel norm-chain scratch
__device__ float g_v1a[ROWS_BI], g_v1b[ROWS_BI];
__device__ float g_w1a[ROWS_SP], g_w1b[ROWS_SP];
// per-pixel norms
__device__ float g_nbi[NPIX];
__device__ float g_nsp[NPIX];

__device__ __forceinline__ uint4* hbi(int i) { return i == 0 ? g_hb0 : (i == 1 ? g_hb1 : g_hb2); }
__device__ __forceinline__ uint4* hsp(int i) { return i == 0 ? g_hs0 : (i == 1 ? g_hs1 : g_hs2); }
__device__ __forceinline__ float* n1bi(int i) { return i ? g_v1b : g_v1a; }
__device__ __forceinline__ float* n1sp(int i) { return i ? g_w1b : g_w1a; }

__device__ __forceinline__ unsigned pack2(float a, float b) {
    __half2 h = __floats2half2_rn(a, b);
    return *reinterpret_cast<unsigned*>(&h);
}
__device__ __forceinline__ float2 unp2(unsigned u) {
    __half2 h = *reinterpret_cast<__half2*>(&u);
    return __half22float2(h);
}
__device__ __forceinline__ unsigned comb2(unsigned a, unsigned b, unsigned c) {
    float2 fa = unp2(a), fb = unp2(b), fc = unp2(c);
    return pack2(fa.x + 0.5f * (fb.x + fc.x), fa.y + 0.5f * (fb.y + fc.y));
}
__device__ __forceinline__ void red4h(uint4* p, unsigned a, unsigned b, unsigned c, unsigned d) {
    asm volatile("red.global.add.noftz.v4.f16x2 [%0], {%1, %2, %3, %4};"
                 :: "l"(p), "r"(a), "r"(b), "r"(c), "r"(d) : "memory");
}

// FFMA-only e^x for x <= 0 (clamped at -80); avoids the MUFU pipe.
__device__ __forceinline__ float fexp(float x) {
    x = fmaxf(x, -80.0f);
    float t  = x * 1.4426950408889634f;      // log2(e)
    float fl = floorf(t);
    float f  = t - fl;
    // 2^f, f in [0,1): degree-6 Taylor of exp(f*ln2), rel err ~1.7e-5
    float p = 1.5403530e-4f;
    p = p * f + 1.3333558e-3f;
    p = p * f + 9.6181291e-3f;
    p = p * f + 5.5504109e-2f;
    p = p * f + 2.4022651e-1f;
    p = p * f + 6.9314718e-1f;
    p = p * f + 1.0f;
    return __int_as_float(__float_as_int(p) + ((int)fl << 23));
}

// ---------------------------------------------------------------------------

__global__ __launch_bounds__(256) void k_zero_fronts(long long na, long long nb) {
    long long i = (long long)blockIdx.x * blockDim.x + threadIdx.x;
    if (i >= na + nb) return;
    if (i < na) g_v1a[i]      = 0.0f;
    else        g_w1a[i - na] = 0.0f;
}

// 1-ch splat for both lattices + zero two fp16 buffers (uint4 counts)
__global__ __launch_bounds__(256) void k_splat1z(const float* __restrict__ ws_bi,
                                                 const int* __restrict__ os_bi, int N6,
                                                 const float* __restrict__ ws_sp,
                                                 const int* __restrict__ os_sp, int N3,
                                                 int zbi, long long zna,
                                                 int zsp, long long znb) {
    long long i = (long long)blockIdx.x * blockDim.x + threadIdx.x;
    if (i < N6) { atomicAdd(g_v1a + os_bi[i], ws_bi[i]); return; }
    if (i < N6 + N3) { long long j = i - N6; atomicAdd(g_w1a + os_sp[j], ws_sp[j]); return; }
    long long z = i - (N6 + N3);
    uint4 zz = make_uint4(0, 0, 0, 0);
    if (z < zna)            hbi(zbi)[z]       = zz;
    else if (z < zna + znb) hsp(zsp)[z - zna] = zz;
}

__global__ __launch_bounds__(256) void k_blur1_both(int bd, int bs,
                                                    const int* __restrict__ nbr_b, int Mb,
                                                    int sd, int ss,
                                                    const int* __restrict__ nbr_s, int Ms,
                                                    int hassp) {
    int nb = Mb + 1;
    int ns = hassp ? (Ms + 1) : 0;
    int i = blockIdx.x * blockDim.x + threadIdx.x;
    if (i >= nb + ns) return;
    float* dst; const float* src; const int* nbr; int r;
    if (i < nb) { dst = n1bi(bd); src = n1bi(bs); nbr = nbr_b; r = i; }
    else        { dst = n1sp(sd); src = n1sp(ss); nbr = nbr_s; r = i - nb; }
    if (r == 0) { dst[0] = 0.0f; return; }
    int2 nn = ((const int2*)nbr)[r - 1];
    dst[r] = src[r] + 0.5f * (src[nn.x] + src[nn.y]);
}

__global__ __launch_bounds__(256) void k_norm_both(int bvid, int svid,
                                                   const float* __restrict__ ws_bi,
                                                   const int* __restrict__ os_bi,
                                                   const float* __restrict__ ws_sp,
                                                   const int* __restrict__ os_sp,
                                                   int N, float a_bi, float a_sp) {
    int n = blockIdx.x * blockDim.x + threadIdx.x;
    if (n >= N) return;
    const float* vb = n1bi(bvid);
    float s = 0.0f;
#pragma unroll
    for (int j = 0; j < 6; j++) s += ws_bi[n * 6 + j] * vb[os_bi[n * 6 + j]];
    g_nbi[n] = 1.0f / (sqrtf(a_bi * s) + 1e-20f);
    const float* vs = n1sp(svid);
    float t = 0.0f;
#pragma unroll
    for (int j = 0; j < 3; j++) t += ws_sp[n * 3 + j] * vs[os_sp[n * 3 + j]];
    g_nsp[n] = 1.0f / (sqrtf(a_sp * t) + 1e-20f);
}

// ---- fp16 24-ch blur, bi+sp merged, optional zero tail ----
__global__ __launch_bounds__(256) void k_blurHz(int bd, int bs,
                                                const int* __restrict__ nbr_b, int Mb,
                                                int sd, int ss,
                                                const int* __restrict__ nbr_s, int Ms,
                                                int hassp,
                                                int zbi, long long zna,
                                                int zsp, long long znb) {
    long long nbt = (long long)(Mb + 1) * GRPH;
    long long nst = hassp ? (long long)(Ms + 1) * GRPH : 0;
    long long idx = (long long)blockIdx.x * blockDim.x + threadIdx.x;
    if (idx < nbt + nst) {
        uint4* dst; const uint4* src; const int* nbr; long long rel;
        if (idx < nbt) { dst = hbi(bd); src = hbi(bs); nbr = nbr_b; rel = idx; }
        else           { dst = hsp(sd); src = hsp(ss); nbr = nbr_s; rel = idx - nbt; }
        int r = (int)(rel / GRPH);
        int g = (int)(rel % GRPH);
        if (r == 0) { dst[g] = make_uint4(0, 0, 0, 0); return; }
        int2 nn = ((const int2*)nbr)[r - 1];
        uint4 a = src[rel];
        uint4 b = src[(long long)nn.x * GRPH + g];
        uint4 c = src[(long long)nn.y * GRPH + g];
        uint4 o;
        o.x = comb2(a.x, b.x, c.x);
        o.y = comb2(a.y, b.y, c.y);
        o.z = comb2(a.z, b.z, c.z);
        o.w = comb2(a.w, b.w, c.w);
        dst[rel] = o;
        return;
    }
    long long z = idx - (nbt + nst);
    uint4 zz = make_uint4(0, 0, 0, 0);
    if (z < zna)            hbi(zbi)[z]       = zz;
    else if (z < zna + znb) hsp(zsp)[z - zna] = zz;
}

// ---- fused slice(bi)+slice(sp)+softmax+Q (+splat into next fp16 buffers) ----
// ONE THREAD PER PIXEL: no idle lanes, no shuffles, 21 exps, high gather MLP.
__global__ __launch_bounds__(256) void k_update_splat(
        const float* __restrict__ u, float* __restrict__ extout,
        const float* __restrict__ ws_bi, const int* __restrict__ os_bi,
        const float* __restrict__ ws_sp, const int* __restrict__ os_sp,
        int N, int usepair, int to_ext, int do_splat,
        int rd_bi, int rd_sp, int wr_bi, int wr_sp, float cb, float cs) {
    int n = blockIdx.x * blockDim.x + threadIdx.x;
    if (n >= N) return;

    float nb = g_nbi[n];
    float ns = g_nsp[n];
    float wbj[6]; int obj[6];
    float wsj[3]; int osj[3];
    {
        const float2* w2 = (const float2*)(ws_bi + n * 6);
        const int2*   o2 = (const int2*)(os_bi + n * 6);
#pragma unroll
        for (int j = 0; j < 3; j++) {
            float2 w = w2[j]; int2 o = o2[j];
            wbj[2 * j] = w.x; wbj[2 * j + 1] = w.y;
            obj[2 * j] = o.x; obj[2 * j + 1] = o.y;
        }
#pragma unroll
        for (int j = 0; j < 3; j++) { wsj[j] = ws_sp[n * 3 + j]; osj[j] = os_sp[n * 3 + j]; }
    }

    float l[CC];
#pragma unroll
    for (int k = 0; k < CC; k++) l[k] = 0.0f;

    if (usepair) {
        const uint4* vb = hbi(rd_bi);
        float pb = cb * nb;
#pragma unroll
        for (int j = 0; j < 6; j++) {
            float w = wbj[j] * pb;
            const uint4* row = vb + (long long)obj[j] * GRPH;
            uint4 v0 = row[0], v1 = row[1], v2 = row[2];
            unsigned h[6] = {v0.x, v0.y, v0.z, v0.w, v1.x, v1.y};
#pragma unroll
            for (int k = 0; k < 6; k++) { float2 f = unp2(h[k]); l[2*k] += w*f.x; l[2*k+1] += w*f.y; }
            float2 f6 = unp2(v1.z), f7 = unp2(v1.w), f8 = unp2(v2.x), f9 = unp2(v2.y), fa = unp2(v2.z);
            l[12] += w*f6.x; l[13] += w*f6.y; l[14] += w*f7.x; l[15] += w*f7.y;
            l[16] += w*f8.x; l[17] += w*f8.y; l[18] += w*f9.x; l[19] += w*f9.y;
            l[20] += w*fa.x;
        }
        const uint4* vs = hsp(rd_sp);
        float ps = cs * ns;
#pragma unroll
        for (int j = 0; j < 3; j++) {
            float w = wsj[j] * ps;
            const uint4* row = vs + (long long)osj[j] * GRPH;
            uint4 v0 = row[0], v1 = row[1], v2 = row[2];
            unsigned h[6] = {v0.x, v0.y, v0.z, v0.w, v1.x, v1.y};
#pragma unroll
            for (int k = 0; k < 6; k++) { float2 f = unp2(h[k]); l[2*k] += w*f.x; l[2*k+1] += w*f.y; }
            float2 f6 = unp2(v1.z), f7 = unp2(v1.w), f8 = unp2(v2.x), f9 = unp2(v2.y), fa = unp2(v2.z);
            l[12] += w*f6.x; l[13] += w*f6.y; l[14] += w*f7.x; l[15] += w*f7.y;
            l[16] += w*f8.x; l[17] += w*f8.y; l[18] += w*f9.x; l[19] += w*f9.y;
            l[20] += w*fa.x;
        }
    }

    long long ub = (long long)n * CC;
#pragma unroll
    for (int k = 0; k < CC; k++) l[k] -= u[ub + k];

    float mx = l[0];
#pragma unroll
    for (int k = 1; k < CC; k++) mx = fmaxf(mx, l[k]);
    float s = 0.0f;
#pragma unroll
    for (int k = 0; k < CC; k++) { l[k] = fexp(l[k] - mx); s += l[k]; }
    float inv = 1.0f / s;
#pragma unroll
    for (int k = 0; k < CC; k++) l[k] *= inv;      // l[] now holds Q

    if (to_ext) {
#pragma unroll
        for (int k = 0; k < CC; k++) extout[ub + k] = l[k];
    }
    if (do_splat) {
        uint4* vb = hbi(wr_bi);
#pragma unroll
        for (int j = 0; j < 6; j++) {
            float w = wbj[j] * nb;
            red4h(vb + (long long)obj[j] * GRPH,
                  pack2(w*l[0], w*l[1]),  pack2(w*l[2], w*l[3]),
                  pack2(w*l[4], w*l[5]),  pack2(w*l[6], w*l[7]));
            red4h(vb + (long long)obj[j] * GRPH + 1,
                  pack2(w*l[8], w*l[9]),  pack2(w*l[10], w*l[11]),
                  pack2(w*l[12], w*l[13]), pack2(w*l[14], w*l[15]));
            red4h(vb + (long long)obj[j] * GRPH + 2,
                  pack2(w*l[16], w*l[17]), pack2(w*l[18], w*l[19]),
                  pack2(w*l[20], 0.0f),    0u);
        }
        uint4* vs = hsp(wr_sp);
#pragma unroll
        for (int j = 0; j < 3; j++) {
            float w = wsj[j] * ns;
            red4h(vs + (long long)osj[j] * GRPH,
                  pack2(w*l[0], w*l[1]),  pack2(w*l[2], w*l[3]),
                  pack2(w*l[4], w*l[5]),  pack2(w*l[6], w*l[7]));
            red4h(vs + (long long)osj[j] * GRPH + 1,
                  pack2(w*l[8], w*l[9]),  pack2(w*l[10], w*l[11]),
                  pack2(w*l[12], w*l[13]), pack2(w*l[14], w*l[15]));
            red4h(vs + (long long)osj[j] * GRPH + 2,
                  pack2(w*l[16], w*l[17]), pack2(w*l[18], w*l[19]),
                  pack2(w*l[20], 0.0f),    0u);
        }
    }
}

// ---------------------------------------------------------------------------

static inline unsigned gridFor(long long n) { return (unsigned)((n + 255) / 256); }

extern "C" void kernel_launch(void* const* d_in, const int* in_sizes, int n_in,
                              void* d_out, int out_size) {
    const float* unary  = (const float*)d_in[0];
    const float* ws_bi  = (const float*)d_in[1];
    const float* ws_sp  = (const float*)d_in[2];
    const int*   os_bi  = (const int*)  d_in[3];
    const int*   os_sp  = (const int*)  d_in[4];
    const int*   nbr_bi = (const int*)  d_in[5];
    const int*   nbr_sp = (const int*)  d_in[6];
    float*       out    = (float*)d_out;

    const int N   = in_sizes[1] / 6;
    const int Mbi = in_sizes[5] / 12;
    const int Msp = in_sizes[6] / 6;
    const float ALPHA_BI = 32.0f / 33.0f;  // 1/(1+2^-5)
    const float ALPHA_SP = 0.8f;           // 1/(1+2^-2)
    const float CB = 10.0f * ALPHA_BI;
    const float CS = 3.0f  * ALPHA_SP;
    const int B = 256;

    const long long NBH = (long long)(Mbi + 1) * GRPH;   // fp16 buffer in uint4s
    const long long NSH = (long long)(Msp + 1) * GRPH;

    // ---- prologue: normalization constants (fp32 1-channel chain) ----
    k_zero_fronts<<<gridFor((Mbi + 1) + (Msp + 1)), B>>>(Mbi + 1, Msp + 1);
    k_splat1z<<<gridFor((long long)N * 9 + NBH + NSH), B>>>(
        ws_bi, os_bi, N * 6, ws_sp, os_sp, N * 3, 2, NBH, 2, NSH);
    {
        int cb_ = 0, cs_ = 0;
        for (int j = 0; j < 6; j++) {
            int hassp = (j < 3);
            int bd = 1 - cb_;
            int sd = 1 - cs_;
            long long tot = (Mbi + 1) + (hassp ? (Msp + 1) : 0);
            k_blur1_both<<<gridFor(tot), B>>>(bd, cb_, nbr_bi + (long long)j * Mbi * 2, Mbi,
                                              sd, cs_, nbr_sp + (long long)j * Msp * 2, Msp, hassp);
            cb_ = bd;
            if (hassp) cs_ = sd;
        }
        // bi final in 0 (6 flips), sp final in 1 (3 flips)
        k_norm_both<<<gridFor(N), B>>>(cb_, cs_, ws_bi, os_bi, ws_sp, os_sp, N, ALPHA_BI, ALPHA_SP);
    }

    // ---- initial Q = softmax(-u), splat into bi2 / sp2 (zeroed in k_splat1z) ----
    k_update_splat<<<gridFor(N), B>>>(
        unary, out, ws_bi, os_bi, ws_sp, os_sp, N,
        /*usepair=*/0, /*to_ext=*/0, /*do_splat=*/1,
        0, 0, /*wr_bi=*/2, /*wr_sp=*/2, CB, CS);

    // ---- mean-field iterations (triple-buffer rotation) ----
    int sB = 2, tB = 0, zB = 1;   // bi: splat-src / pong / to-zero
    int sS = 2, tS = 0, zS = 1;   // sp
    for (int it = 0; it < 5; it++) {
        int c = sB, csp = sS;
        for (int j = 0; j < 6; j++) {
            int hassp = (j < 3);
            int d   = (c   == sB) ? tB : sB;
            int dsp = (csp == sS) ? tS : sS;
            long long tot = NBH + (hassp ? NSH : 0) + ((j == 0) ? (NBH + NSH) : 0);
            if (j == 0) {
                k_blurHz<<<gridFor(tot), B>>>(d, c, nbr_bi + (long long)j * Mbi * 2, Mbi,
                                              dsp, csp, nbr_sp + (long long)j * Msp * 2, Msp,
                                              hassp, zB, NBH, zS, NSH);
            } else {
                k_blurHz<<<gridFor(tot), B>>>(d, c, nbr_bi + (long long)j * Mbi * 2, Mbi,
                                              dsp, csp, nbr_sp + (long long)j * Msp * 2, Msp,
                                              hassp, 0, 0, 0, 0);
            }
            c = d;
            if (hassp) csp = dsp;
        }
        // bi result in sB (6 flips), sp result in tS (3 flips)
        if (it < 4) {
            k_update_splat<<<gridFor(N), B>>>(
                unary, out, ws_bi, os_bi, ws_sp, os_sp, N,
                /*usepair=*/1, /*to_ext=*/0, /*do_splat=*/1,
                sB, tS, /*wr_bi=*/zB, /*wr_sp=*/zS, CB, CS);
            int nB_ = zB; zB = sB; sB = nB_;                   // tB unchanged
            int nS_ = zS; zS = tS; tS = sS; sS = nS_;
        } else {
            k_update_splat<<<gridFor(N), B>>>(
                unary, out, ws_bi, os_bi, ws_sp, os_sp, N,
                /*usepair=*/1, /*to_ext=*/1, /*do_splat=*/0,
                sB, tS, 0, 0, CB, CS);
        }
    }
}

// round 9
// speedup vs baseline: 1.2130x; 1.2130x over previous
#include <cuda_runtime.h>
#include <cuda_fp16.h>
#include <math.h>

// ---------------------------------------------------------------------------
// DenseCRF mean-field with permutohedral lattice filtering.
// 21-ch lattice buffers stored as fp16 (24 padded ch = 48B rows = 3 uint4),
// fp32 compute, fp32 1-channel normalization chain, fused update+splat
// (4 lanes/pixel, FFMA-only exp), merged bi/sp launches,
// triple-buffered with zero riding in blur pass 0.   [R6 structure + fexp]
// ---------------------------------------------------------------------------

#define CC 21
#define GRPH 3                      // uint4 groups per fp16 row (8 halves each)
static constexpr int       NPIX    = 512 * 512;
static constexpr long long ROWS_BI = 6LL * NPIX + 1;
static constexpr long long ROWS_SP = 3LL * NPIX + 1;

// fp16 value buffers (uint4 = 8 halves)
__device__ uint4 g_hb0[ROWS_BI * GRPH];
__device__ uint4 g_hb1[ROWS_BI * GRPH];
__device__ uint4 g_hb2[ROWS_BI * GRPH];
__device__ uint4 g_hs0[ROWS_SP * GRPH];
__device__ uint4 g_hs1[ROWS_SP * GRPH];
__device__ uint4 g_hs2[ROWS_SP * GRPH];
// fp32 1-channel norm-chain scratch
__device__ float g_v1a[ROWS_BI], g_v1b[ROWS_BI];
__device__ float g_w1a[ROWS_SP], g_w1b[ROWS_SP];
// per-pixel norms
__device__ float g_nbi[NPIX];
__device__ float g_nsp[NPIX];

__device__ __forceinline__ uint4* hbi(int i) { return i == 0 ? g_hb0 : (i == 1 ? g_hb1 : g_hb2); }
__device__ __forceinline__ uint4* hsp(int i) { return i == 0 ? g_hs0 : (i == 1 ? g_hs1 : g_hs2); }
__device__ __forceinline__ float* n1bi(int i) { return i ? g_v1b : g_v1a; }
__device__ __forceinline__ float* n1sp(int i) { return i ? g_w1b : g_w1a; }

__device__ __forceinline__ unsigned pack2(float a, float b) {
    __half2 h = __floats2half2_rn(a, b);
    return *reinterpret_cast<unsigned*>(&h);
}
__device__ __forceinline__ float2 unp2(unsigned u) {
    __half2 h = *reinterpret_cast<__half2*>(&u);
    return __half22float2(h);
}
__device__ __forceinline__ unsigned comb2(unsigned a, unsigned b, unsigned c) {
    float2 fa = unp2(a), fb = unp2(b), fc = unp2(c);
    return pack2(fa.x + 0.5f * (fb.x + fc.x), fa.y + 0.5f * (fb.y + fc.y));
}
__device__ __forceinline__ void red4h(uint4* p, unsigned a, unsigned b, unsigned c, unsigned d) {
    asm volatile("red.global.add.noftz.v4.f16x2 [%0], {%1, %2, %3, %4};"
                 :: "l"(p), "r"(a), "r"(b), "r"(c), "r"(d) : "memory");
}

// FFMA-only e^x for x <= 0 (clamped at -80); avoids the MUFU pipe.
__device__ __forceinline__ float fexp(float x) {
    x = fmaxf(x, -80.0f);
    float t  = x * 1.4426950408889634f;      // log2(e)
    float fl = floorf(t);
    float f  = t - fl;
    float p = 1.5403530e-4f;
    p = p * f + 1.3333558e-3f;
    p = p * f + 9.6181291e-3f;
    p = p * f + 5.5504109e-2f;
    p = p * f + 2.4022651e-1f;
    p = p * f + 6.9314718e-1f;
    p = p * f + 1.0f;
    return __int_as_float(__float_as_int(p) + ((int)fl << 23));
}

// ---------------------------------------------------------------------------

__global__ __launch_bounds__(256) void k_zero_fronts(long long na, long long nb) {
    long long i = (long long)blockIdx.x * blockDim.x + threadIdx.x;
    if (i >= na + nb) return;
    if (i < na) g_v1a[i]      = 0.0f;
    else        g_w1a[i - na] = 0.0f;
}

// 1-ch splat for both lattices + zero two fp16 buffers (uint4 counts)
__global__ __launch_bounds__(256) void k_splat1z(const float* __restrict__ ws_bi,
                                                 const int* __restrict__ os_bi, int N6,
                                                 const float* __restrict__ ws_sp,
                                                 const int* __restrict__ os_sp, int N3,
                                                 int zbi, long long zna,
                                                 int zsp, long long znb) {
    long long i = (long long)blockIdx.x * blockDim.x + threadIdx.x;
    if (i < N6) { atomicAdd(g_v1a + os_bi[i], ws_bi[i]); return; }
    if (i < N6 + N3) { long long j = i - N6; atomicAdd(g_w1a + os_sp[j], ws_sp[j]); return; }
    long long z = i - (N6 + N3);
    uint4 zz = make_uint4(0, 0, 0, 0);
    if (z < zna)            hbi(zbi)[z]       = zz;
    else if (z < zna + znb) hsp(zsp)[z - zna] = zz;
}

__global__ __launch_bounds__(256) void k_blur1_both(int bd, int bs,
                                                    const int* __restrict__ nbr_b, int Mb,
                                                    int sd, int ss,
                                                    const int* __restrict__ nbr_s, int Ms,
                                                    int hassp) {
    int nb = Mb + 1;
    int ns = hassp ? (Ms + 1) : 0;
    int i = blockIdx.x * blockDim.x + threadIdx.x;
    if (i >= nb + ns) return;
    float* dst; const float* src; const int* nbr; int r;
    if (i < nb) { dst = n1bi(bd); src = n1bi(bs); nbr = nbr_b; r = i; }
    else        { dst = n1sp(sd); src = n1sp(ss); nbr = nbr_s; r = i - nb; }
    if (r == 0) { dst[0] = 0.0f; return; }
    int2 nn = ((const int2*)nbr)[r - 1];
    dst[r] = src[r] + 0.5f * (src[nn.x] + src[nn.y]);
}

__global__ __launch_bounds__(256) void k_norm_both(int bvid, int svid,
                                                   const float* __restrict__ ws_bi,
                                                   const int* __restrict__ os_bi,
                                                   const float* __restrict__ ws_sp,
                                                   const int* __restrict__ os_sp,
                                                   int N, float a_bi, float a_sp) {
    int n = blockIdx.x * blockDim.x + threadIdx.x;
    if (n >= N) return;
    const float* vb = n1bi(bvid);
    float s = 0.0f;
#pragma unroll
    for (int j = 0; j < 6; j++) s += ws_bi[n * 6 + j] * vb[os_bi[n * 6 + j]];
    g_nbi[n] = 1.0f / (sqrtf(a_bi * s) + 1e-20f);
    const float* vs = n1sp(svid);
    float t = 0.0f;
#pragma unroll
    for (int j = 0; j < 3; j++) t += ws_sp[n * 3 + j] * vs[os_sp[n * 3 + j]];
    g_nsp[n] = 1.0f / (sqrtf(a_sp * t) + 1e-20f);
}

// ---- fp16 24-ch blur, bi+sp merged, optional zero tail ----
__global__ __launch_bounds__(256) void k_blurHz(int bd, int bs,
                                                const int* __restrict__ nbr_b, int Mb,
                                                int sd, int ss,
                                                const int* __restrict__ nbr_s, int Ms,
                                                int hassp,
                                                int zbi, long long zna,
                                                int zsp, long long znb) {
    long long nbt = (long long)(Mb + 1) * GRPH;
    long long nst = hassp ? (long long)(Ms + 1) * GRPH : 0;
    long long idx = (long long)blockIdx.x * blockDim.x + threadIdx.x;
    if (idx < nbt + nst) {
        uint4* dst; const uint4* src; const int* nbr; long long rel;
        if (idx < nbt) { dst = hbi(bd); src = hbi(bs); nbr = nbr_b; rel = idx; }
        else           { dst = hsp(sd); src = hsp(ss); nbr = nbr_s; rel = idx - nbt; }
        int r = (int)(rel / GRPH);
        int g = (int)(rel % GRPH);
        if (r == 0) { dst[g] = make_uint4(0, 0, 0, 0); return; }
        int2 nn = ((const int2*)nbr)[r - 1];
        uint4 a = src[rel];
        uint4 b = src[(long long)nn.x * GRPH + g];
        uint4 c = src[(long long)nn.y * GRPH + g];
        uint4 o;
        o.x = comb2(a.x, b.x, c.x);
        o.y = comb2(a.y, b.y, c.y);
        o.z = comb2(a.z, b.z, c.z);
        o.w = comb2(a.w, b.w, c.w);
        dst[rel] = o;
        return;
    }
    long long z = idx - (nbt + nst);
    uint4 zz = make_uint4(0, 0, 0, 0);
    if (z < zna)            hbi(zbi)[z]       = zz;
    else if (z < zna + znb) hsp(zsp)[z - zna] = zz;
}

// ---- fused slice(bi)+slice(sp)+softmax+Q (+splat into next fp16 buffers) ----
// 4 lanes per pixel; lanes 0..2 own 8 channels each (24 padded), lane 3 idle.
__global__ __launch_bounds__(256) void k_update_splat(
        const float* __restrict__ u, float* __restrict__ extout,
        const float* __restrict__ ws_bi, const int* __restrict__ os_bi,
        const float* __restrict__ ws_sp, const int* __restrict__ os_sp,
        int N, int usepair, int to_ext, int do_splat,
        int rd_bi, int rd_sp, int wr_bi, int wr_sp, float cb, float cs) {
    int tid = blockIdx.x * blockDim.x + threadIdx.x;
    int n = tid >> 2;
    int g = tid & 3;
    if (n >= N) return;
    bool act = (g < GRPH);

    float nb = g_nbi[n];
    float ns = g_nsp[n];
    float wbj[6]; int obj[6];
    float wsj[3]; int osj[3];
#pragma unroll
    for (int j = 0; j < 6; j++) { wbj[j] = ws_bi[n * 6 + j]; obj[j] = os_bi[n * 6 + j]; }
#pragma unroll
    for (int j = 0; j < 3; j++) { wsj[j] = ws_sp[n * 3 + j]; osj[j] = os_sp[n * 3 + j]; }

    float l[8];
#pragma unroll
    for (int k = 0; k < 8; k++) l[k] = -1e30f;

    if (act) {
        float acc[8];
#pragma unroll
        for (int k = 0; k < 8; k++) acc[k] = 0.0f;
        if (usepair) {
            const uint4* vb = hbi(rd_bi);
            float pb = cb * nb;
#pragma unroll
            for (int j = 0; j < 6; j++) {
                float w = wbj[j] * pb;
                uint4 v = vb[(long long)obj[j] * GRPH + g];
                float2 f0 = unp2(v.x), f1 = unp2(v.y), f2 = unp2(v.z), f3 = unp2(v.w);
                acc[0] += w * f0.x; acc[1] += w * f0.y;
                acc[2] += w * f1.x; acc[3] += w * f1.y;
                acc[4] += w * f2.x; acc[5] += w * f2.y;
                acc[6] += w * f3.x; acc[7] += w * f3.y;
            }
            const uint4* vs = hsp(rd_sp);
            float ps = cs * ns;
#pragma unroll
            for (int j = 0; j < 3; j++) {
                float w = wsj[j] * ps;
                uint4 v = vs[(long long)osj[j] * GRPH + g];
                float2 f0 = unp2(v.x), f1 = unp2(v.y), f2 = unp2(v.z), f3 = unp2(v.w);
                acc[0] += w * f0.x; acc[1] += w * f0.y;
                acc[2] += w * f1.x; acc[3] += w * f1.y;
                acc[4] += w * f2.x; acc[5] += w * f2.y;
                acc[6] += w * f3.x; acc[7] += w * f3.y;
            }
        }
        int c0 = g * 8;
        long long ub = (long long)n * CC + c0;
#pragma unroll
        for (int k = 0; k < 8; k++)
            if (c0 + k < CC) l[k] = acc[k] - u[ub + k];
    }

    // softmax across the 4-lane group (24 padded channels; pads -> exp = 0)
    float mx = l[0];
#pragma unroll
    for (int k = 1; k < 8; k++) mx = fmaxf(mx, l[k]);
#pragma unroll
    for (int d = 1; d < 4; d <<= 1)
        mx = fmaxf(mx, __shfl_xor_sync(0xffffffffu, mx, d, 4));
    float e[8], s = 0.0f;
#pragma unroll
    for (int k = 0; k < 8; k++) { e[k] = fexp(l[k] - mx); s += e[k]; }
#pragma unroll
    for (int d = 1; d < 4; d <<= 1)
        s += __shfl_xor_sync(0xffffffffu, s, d, 4);
    float inv = 1.0f / s;

    if (act) {
        float q[8];
#pragma unroll
        for (int k = 0; k < 8; k++) q[k] = e[k] * inv;
        if (to_ext) {
            int c0 = g * 8;
            long long ob = (long long)n * CC + c0;
#pragma unroll
            for (int k = 0; k < 8; k++)
                if (c0 + k < CC) extout[ob + k] = q[k];
        }
        if (do_splat) {
            uint4* vb = hbi(wr_bi);
#pragma unroll
            for (int j = 0; j < 6; j++) {
                float w = wbj[j] * nb;
                red4h(vb + (long long)obj[j] * GRPH + g,
                      pack2(w * q[0], w * q[1]), pack2(w * q[2], w * q[3]),
                      pack2(w * q[4], w * q[5]), pack2(w * q[6], w * q[7]));
            }
            uint4* vs = hsp(wr_sp);
#pragma unroll
            for (int j = 0; j < 3; j++) {
                float w = wsj[j] * ns;
                red4h(vs + (long long)osj[j] * GRPH + g,
                      pack2(w * q[0], w * q[1]), pack2(w * q[2], w * q[3]),
                      pack2(w * q[4], w * q[5]), pack2(w * q[6], w * q[7]));
            }
        }
    }
}

// ---------------------------------------------------------------------------

static inline unsigned gridFor(long long n) { return (unsigned)((n + 255) / 256); }

extern "C" void kernel_launch(void* const* d_in, const int* in_sizes, int n_in,
                              void* d_out, int out_size) {
    const float* unary  = (const float*)d_in[0];
    const float* ws_bi  = (const float*)d_in[1];
    const float* ws_sp  = (const float*)d_in[2];
    const int*   os_bi  = (const int*)  d_in[3];
    const int*   os_sp  = (const int*)  d_in[4];
    const int*   nbr_bi = (const int*)  d_in[5];
    const int*   nbr_sp = (const int*)  d_in[6];
    float*       out    = (float*)d_out;

    const int N   = in_sizes[1] / 6;
    const int Mbi = in_sizes[5] / 12;
    const int Msp = in_sizes[6] / 6;
    const float ALPHA_BI = 32.0f / 33.0f;  // 1/(1+2^-5)
    const float ALPHA_SP = 0.8f;           // 1/(1+2^-2)
    const float CB = 10.0f * ALPHA_BI;
    const float CS = 3.0f  * ALPHA_SP;
    const int B = 256;

    const long long NBH = (long long)(Mbi + 1) * GRPH;   // fp16 buffer in uint4s
    const long long NSH = (long long)(Msp + 1) * GRPH;

    // ---- prologue: normalization constants (fp32 1-channel chain) ----
    k_zero_fronts<<<gridFor((Mbi + 1) + (Msp + 1)), B>>>(Mbi + 1, Msp + 1);
    k_splat1z<<<gridFor((long long)N * 9 + NBH + NSH), B>>>(
        ws_bi, os_bi, N * 6, ws_sp, os_sp, N * 3, 2, NBH, 2, NSH);
    {
        int cb_ = 0, cs_ = 0;
        for (int j = 0; j < 6; j++) {
            int hassp = (j < 3);
            int bd = 1 - cb_;
            int sd = 1 - cs_;
            long long tot = (Mbi + 1) + (hassp ? (Msp + 1) : 0);
            k_blur1_both<<<gridFor(tot), B>>>(bd, cb_, nbr_bi + (long long)j * Mbi * 2, Mbi,
                                              sd, cs_, nbr_sp + (long long)j * Msp * 2, Msp, hassp);
            cb_ = bd;
            if (hassp) cs_ = sd;
        }
        // bi final in 0 (6 flips), sp final in 1 (3 flips)
        k_norm_both<<<gridFor(N), B>>>(cb_, cs_, ws_bi, os_bi, ws_sp, os_sp, N, ALPHA_BI, ALPHA_SP);
    }

    // ---- initial Q = softmax(-u), splat into bi2 / sp2 (zeroed in k_splat1z) ----
    k_update_splat<<<gridFor((long long)N * 4), B>>>(
        unary, out, ws_bi, os_bi, ws_sp, os_sp, N,
        /*usepair=*/0, /*to_ext=*/0, /*do_splat=*/1,
        0, 0, /*wr_bi=*/2, /*wr_sp=*/2, CB, CS);

    // ---- mean-field iterations (triple-buffer rotation) ----
    int sB = 2, tB = 0, zB = 1;   // bi: splat-src / pong / to-zero
    int sS = 2, tS = 0, zS = 1;   // sp
    for (int it = 0; it < 5; it++) {
        int c = sB, csp = sS;
        for (int j = 0; j < 6; j++) {
            int hassp = (j < 3);
            int d   = (c   == sB) ? tB : sB;
            int dsp = (csp == sS) ? tS : sS;
            long long tot = NBH + (hassp ? NSH : 0) + ((j == 0) ? (NBH + NSH) : 0);
            if (j == 0) {
                k_blurHz<<<gridFor(tot), B>>>(d, c, nbr_bi + (long long)j * Mbi * 2, Mbi,
                                              dsp, csp, nbr_sp + (long long)j * Msp * 2, Msp,
                                              hassp, zB, NBH, zS, NSH);
            } else {
                k_blurHz<<<gridFor(tot), B>>>(d, c, nbr_bi + (long long)j * Mbi * 2, Mbi,
                                              dsp, csp, nbr_sp + (long long)j * Msp * 2, Msp,
                                              hassp, 0, 0, 0, 0);
            }
            c = d;
            if (hassp) csp = dsp;
        }
        // bi result in sB (6 flips), sp result in tS (3 flips)
        if (it < 4) {
            k_update_splat<<<gridFor((long long)N * 4), B>>>(
                unary, out, ws_bi, os_bi, ws_sp, os_sp, N,
                /*usepair=*/1, /*to_ext=*/0, /*do_splat=*/1,
                sB, tS, /*wr_bi=*/zB, /*wr_sp=*/zS, CB, CS);
            int nB_ = zB; zB = sB; sB = nB_;                   // tB unchanged
            int nS_ = zS; zS = tS; tS = sS; sS = nS_;
        } else {
            k_update_splat<<<gridFor((long long)N * 4), B>>>(
                unary, out, ws_bi, os_bi, ws_sp, os_sp, N,
                /*usepair=*/1, /*to_ext=*/1, /*do_splat=*/0,
                sB, tS, 0, 0, CB, CS);
        }
    }
}

// round 11
// speedup vs baseline: 1.2295x; 1.0136x over previous
#include <cuda_runtime.h>
#include <cuda_fp16.h>
#include <math.h>

// ---------------------------------------------------------------------------
// DenseCRF mean-field with permutohedral lattice filtering.
// 21-ch lattice buffers stored as fp16 (24 padded ch = 48B rows = 3 uint4),
// fp32 compute, fp32 1-channel normalization chain, fused update+splat
// (4 lanes/pixel), merged bi/sp launches, triple-buffered with zero riding
// in blur pass 0, nbr L2-prefetch riding in the prologue splat, norm
// computation folded into the initial update.
// ---------------------------------------------------------------------------

#define CC 21
#define GRPH 3                      // uint4 groups per fp16 row (8 halves each)
static constexpr int       NPIX    = 512 * 512;
static constexpr long long ROWS_BI = 6LL * NPIX + 1;
static constexpr long long ROWS_SP = 3LL * NPIX + 1;

// fp16 value buffers (uint4 = 8 halves)
__device__ uint4 g_hb0[ROWS_BI * GRPH];
__device__ uint4 g_hb1[ROWS_BI * GRPH];
__device__ uint4 g_hb2[ROWS_BI * GRPH];
__device__ uint4 g_hs0[ROWS_SP * GRPH];
__device__ uint4 g_hs1[ROWS_SP * GRPH];
__device__ uint4 g_hs2[ROWS_SP * GRPH];
// fp32 1-channel norm-chain scratch
__device__ float g_v1a[ROWS_BI], g_v1b[ROWS_BI];
__device__ float g_w1a[ROWS_SP], g_w1b[ROWS_SP];
// per-pixel norms
__device__ float g_nbi[NPIX];
__device__ float g_nsp[NPIX];
__device__ int   g_dummy;

__device__ __forceinline__ uint4* hbi(int i) { return i == 0 ? g_hb0 : (i == 1 ? g_hb1 : g_hb2); }
__device__ __forceinline__ uint4* hsp(int i) { return i == 0 ? g_hs0 : (i == 1 ? g_hs1 : g_hs2); }
__device__ __forceinline__ float* n1bi(int i) { return i ? g_v1b : g_v1a; }
__device__ __forceinline__ float* n1sp(int i) { return i ? g_w1b : g_w1a; }

__device__ __forceinline__ unsigned pack2(float a, float b) {
    __half2 h = __floats2half2_rn(a, b);
    return *reinterpret_cast<unsigned*>(&h);
}
__device__ __forceinline__ float2 unp2(unsigned u) {
    __half2 h = *reinterpret_cast<__half2*>(&u);
    return __half22float2(h);
}
__device__ __forceinline__ unsigned comb2(unsigned a, unsigned b, unsigned c) {
    float2 fa = unp2(a), fb = unp2(b), fc = unp2(c);
    return pack2(fa.x + 0.5f * (fb.x + fc.x), fa.y + 0.5f * (fb.y + fc.y));
}
__device__ __forceinline__ void red4h(uint4* p, unsigned a, unsigned b, unsigned c, unsigned d) {
    asm volatile("red.global.add.noftz.v4.f16x2 [%0], {%1, %2, %3, %4};"
                 :: "l"(p), "r"(a), "r"(b), "r"(c), "r"(d) : "memory");
}

// FFMA-only e^x for x <= 0 (clamped at -80).
__device__ __forceinline__ float fexp(float x) {
    x = fmaxf(x, -80.0f);
    float t  = x * 1.4426950408889634f;      // log2(e)
    float fl = floorf(t);
    float f  = t - fl;
    float p = 1.5403530e-4f;
    p = p * f + 1.3333558e-3f;
    p = p * f + 9.6181291e-3f;
    p = p * f + 5.5504109e-2f;
    p = p * f + 2.4022651e-1f;
    p = p * f + 6.9314718e-1f;
    p = p * f + 1.0f;
    return __int_as_float(__float_as_int(p) + ((int)fl << 23));
}

// ---------------------------------------------------------------------------

__global__ __launch_bounds__(256) void k_zero_fronts(long long na, long long nb) {
    long long i = (long long)blockIdx.x * blockDim.x + threadIdx.x;
    if (i >= na + nb) return;
    if (i < na) g_v1a[i]      = 0.0f;
    else        g_w1a[i - na] = 0.0f;
}

// 1-ch splat for both lattices + zero two fp16 buffers (uint4 counts)
// + warm nbr arrays into L2 (one 4B read per 128B line).
__global__ __launch_bounds__(256) void k_splat1z(const float* __restrict__ ws_bi,
                                                 const int* __restrict__ os_bi, int N6,
                                                 const float* __restrict__ ws_sp,
                                                 const int* __restrict__ os_sp, int N3,
                                                 int zbi, long long zna,
                                                 int zsp, long long znb,
                                                 const int* __restrict__ nbr_all_bi, long long nwb,
                                                 const int* __restrict__ nbr_all_sp, long long nws) {
    long long i = (long long)blockIdx.x * blockDim.x + threadIdx.x;
    if (i < N6) { atomicAdd(g_v1a + os_bi[i], ws_bi[i]); return; }
    if (i < N6 + N3) { long long j = i - N6; atomicAdd(g_w1a + os_sp[j], ws_sp[j]); return; }
    long long z = i - (N6 + N3);
    uint4 zz = make_uint4(0, 0, 0, 0);
    if (z < zna)            { hbi(zbi)[z]       = zz; return; }
    else if (z < zna + znb) { hsp(zsp)[z - zna] = zz; return; }
    long long p = z - (zna + znb);          // nbr prefetch: 1 word per 32 ints
    int v = 0;
    if (p < nwb)            v = nbr_all_bi[p * 32];
    else if (p < nwb + nws) {
        long long q = (p - nwb) * 32;
        v = nbr_all_sp[q];
    } else return;
    if (v == 0x7fffffff) g_dummy = v;       // never true; defeats DCE
}

__global__ __launch_bounds__(256) void k_blur1_both(int bd, int bs,
                                                    const int* __restrict__ nbr_b, int Mb,
                                                    int sd, int ss,
                                                    const int* __restrict__ nbr_s, int Ms,
                                                    int hassp) {
    int nb = Mb + 1;
    int ns = hassp ? (Ms + 1) : 0;
    int i = blockIdx.x * blockDim.x + threadIdx.x;
    if (i >= nb + ns) return;
    float* dst; const float* src; const int* nbr; int r;
    if (i < nb) { dst = n1bi(bd); src = n1bi(bs); nbr = nbr_b; r = i; }
    else        { dst = n1sp(sd); src = n1sp(ss); nbr = nbr_s; r = i - nb; }
    if (r == 0) { dst[0] = 0.0f; return; }
    int2 nn = ((const int2*)nbr)[r - 1];
    dst[r] = src[r] + 0.5f * (src[nn.x] + src[nn.y]);
}

// ---- fp16 24-ch blur, bi+sp merged, optional zero tail ----
__global__ __launch_bounds__(256) void k_blurHz(int bd, int bs,
                                                const int* __restrict__ nbr_b, int Mb,
                                                int sd, int ss,
                                                const int* __restrict__ nbr_s, int Ms,
                                                int hassp,
                                                int zbi, long long zna,
                                                int zsp, long long znb) {
    long long nbt = (long long)(Mb + 1) * GRPH;
    long long nst = hassp ? (long long)(Ms + 1) * GRPH : 0;
    long long idx = (long long)blockIdx.x * blockDim.x + threadIdx.x;
    if (idx < nbt + nst) {
        uint4* dst; const uint4* src; const int* nbr; long long rel;
        if (idx < nbt) { dst = hbi(bd); src = hbi(bs); nbr = nbr_b; rel = idx; }
        else           { dst = hsp(sd); src = hsp(ss); nbr = nbr_s; rel = idx - nbt; }
        int r = (int)(rel / GRPH);
        int g = (int)(rel % GRPH);
        if (r == 0) { dst[g] = make_uint4(0, 0, 0, 0); return; }
        int2 nn = ((const int2*)nbr)[r - 1];
        uint4 a = src[rel];
        uint4 b = src[(long long)nn.x * GRPH + g];
        uint4 c = src[(long long)nn.y * GRPH + g];
        uint4 o;
        o.x = comb2(a.x, b.x, c.x);
        o.y = comb2(a.y, b.y, c.y);
        o.z = comb2(a.z, b.z, c.z);
        o.w = comb2(a.w, b.w, c.w);
        dst[rel] = o;
        return;
    }
    long long z = idx - (nbt + nst);
    uint4 zz = make_uint4(0, 0, 0, 0);
    if (z < zna)            hbi(zbi)[z]       = zz;
    else if (z < zna + znb) hsp(zsp)[z - zna] = zz;
}

// ---- fused [norm +] slice(bi)+slice(sp)+softmax+Q (+splat into next buffers) ----
// 4 lanes per pixel; lanes 0..2 own 8 channels each (24 padded), lane 3 idle.
__global__ __launch_bounds__(256) void k_update_splat(
        const float* __restrict__ u, float* __restrict__ extout,
        const float* __restrict__ ws_bi, const int* __restrict__ os_bi,
        const float* __restrict__ ws_sp, const int* __restrict__ os_sp,
        int N, int usepair, int to_ext, int do_splat, int do_norm,
        int rd_bi, int rd_sp, int wr_bi, int wr_sp, float cb, float cs,
        int nv_bi, int nv_sp, float a_bi, float a_sp) {
    int tid = blockIdx.x * blockDim.x + threadIdx.x;
    int n = tid >> 2;
    int g = tid & 3;
    if (n >= N) return;
    bool act = (g < GRPH);

    float wbj[6]; int obj[6];
    float wsj[3]; int osj[3];
#pragma unroll
    for (int j = 0; j < 6; j++) { wbj[j] = ws_bi[n * 6 + j]; obj[j] = os_bi[n * 6 + j]; }
#pragma unroll
    for (int j = 0; j < 3; j++) { wsj[j] = ws_sp[n * 3 + j]; osj[j] = os_sp[n * 3 + j]; }

    float nb, ns;
    if (do_norm) {
        float sb = 0.0f, ss_ = 0.0f;
        if (g == 0) {
            const float* vb = n1bi(nv_bi);
#pragma unroll
            for (int j = 0; j < 6; j++) sb += wbj[j] * vb[obj[j]];
            const float* vs = n1sp(nv_sp);
#pragma unroll
            for (int j = 0; j < 3; j++) ss_ += wsj[j] * vs[osj[j]];
            sb  = 1.0f / (sqrtf(a_bi * sb)  + 1e-20f);
            ss_ = 1.0f / (sqrtf(a_sp * ss_) + 1e-20f);
            g_nbi[n] = sb;
            g_nsp[n] = ss_;
        }
        nb = __shfl_sync(0xffffffffu, sb, 0, 4);
        ns = __shfl_sync(0xffffffffu, ss_, 0, 4);
    } else {
        nb = g_nbi[n];
        ns = g_nsp[n];
    }

    float l[8];
#pragma unroll
    for (int k = 0; k < 8; k++) l[k] = -1e30f;

    if (act) {
        float acc[8];
#pragma unroll
        for (int k = 0; k < 8; k++) acc[k] = 0.0f;
        if (usepair) {
            const uint4* vb = hbi(rd_bi);
            float pb = cb * nb;
#pragma unroll
            for (int j = 0; j < 6; j++) {
                float w = wbj[j] * pb;
                uint4 v = vb[(long long)obj[j] * GRPH + g];
                float2 f0 = unp2(v.x), f1 = unp2(v.y), f2 = unp2(v.z), f3 = unp2(v.w);
                acc[0] += w * f0.x; acc[1] += w * f0.y;
                acc[2] += w * f1.x; acc[3] += w * f1.y;
                acc[4] += w * f2.x; acc[5] += w * f2.y;
                acc[6] += w * f3.x; acc[7] += w * f3.y;
            }
            const uint4* vs = hsp(rd_sp);
            float ps = cs * ns;
#pragma unroll
            for (int j = 0; j < 3; j++) {
                float w = wsj[j] * ps;
                uint4 v = vs[(long long)osj[j] * GRPH + g];
                float2 f0 = unp2(v.x), f1 = unp2(v.y), f2 = unp2(v.z), f3 = unp2(v.w);
                acc[0] += w * f0.x; acc[1] += w * f0.y;
                acc[2] += w * f1.x; acc[3] += w * f1.y;
                acc[4] += w * f2.x; acc[5] += w * f2.y;
                acc[6] += w * f3.x; acc[7] += w * f3.y;
            }
        }
        int c0 = g * 8;
        long long ub = (long long)n * CC + c0;
#pragma unroll
        for (int k = 0; k < 8; k++)
            if (c0 + k < CC) l[k] = acc[k] - u[ub + k];
    }

    // softmax across the 4-lane group (24 padded channels; pads -> exp = 0)
    float mx = l[0];
#pragma unroll
    for (int k = 1; k < 8; k++) mx = fmaxf(mx, l[k]);
#pragma unroll
    for (int d = 1; d < 4; d <<= 1)
        mx = fmaxf(mx, __shfl_xor_sync(0xffffffffu, mx, d, 4));
    float e[8], s = 0.0f;
#pragma unroll
    for (int k = 0; k < 8; k++) { e[k] = fexp(l[k] - mx); s += e[k]; }
#pragma unroll
    for (int d = 1; d < 4; d <<= 1)
        s += __shfl_xor_sync(0xffffffffu, s, d, 4);
    float inv = 1.0f / s;

    if (act) {
        float q[8];
#pragma unroll
        for (int k = 0; k < 8; k++) q[k] = e[k] * inv;
        if (to_ext) {
            int c0 = g * 8;
            long long ob = (long long)n * CC + c0;
#pragma unroll
            for (int k = 0; k < 8; k++)
                if (c0 + k < CC) extout[ob + k] = q[k];
        }
        if (do_splat) {
            uint4* vb = hbi(wr_bi);
#pragma unroll
            for (int j = 0; j < 6; j++) {
                float w = wbj[j] * nb;
                red4h(vb + (long long)obj[j] * GRPH + g,
                      pack2(w * q[0], w * q[1]), pack2(w * q[2], w * q[3]),
                      pack2(w * q[4], w * q[5]), pack2(w * q[6], w * q[7]));
            }
            uint4* vs = hsp(wr_sp);
#pragma unroll
            for (int j = 0; j < 3; j++) {
                float w = wsj[j] * ns;
                red4h(vs + (long long)osj[j] * GRPH + g,
                      pack2(w * q[0], w * q[1]), pack2(w * q[2], w * q[3]),
                      pack2(w * q[4], w * q[5]), pack2(w * q[6], w * q[7]));
            }
        }
    }
}

// ---------------------------------------------------------------------------

static inline unsigned gridFor(long long n) { return (unsigned)((n + 255) / 256); }

extern "C" void kernel_launch(void* const* d_in, const int* in_sizes, int n_in,
                              void* d_out, int out_size) {
    const float* unary  = (const float*)d_in[0];
    const float* ws_bi  = (const float*)d_in[1];
    const float* ws_sp  = (const float*)d_in[2];
    const int*   os_bi  = (const int*)  d_in[3];
    const int*   os_sp  = (const int*)  d_in[4];
    const int*   nbr_bi = (const int*)  d_in[5];
    const int*   nbr_sp = (const int*)  d_in[6];
    float*       out    = (float*)d_out;

    const int N   = in_sizes[1] / 6;
    const int Mbi = in_sizes[5] / 12;
    const int Msp = in_sizes[6] / 6;
    const float ALPHA_BI = 32.0f / 33.0f;  // 1/(1+2^-5)
    const float ALPHA_SP = 0.8f;           // 1/(1+2^-2)
    const float CB = 10.0f * ALPHA_BI;
    const float CS = 3.0f  * ALPHA_SP;
    const int B = 256;

    const long long NBH = (long long)(Mbi + 1) * GRPH;   // fp16 buffer in uint4s
    const long long NSH = (long long)(Msp + 1) * GRPH;
    const long long NWB = ((long long)in_sizes[5]) / 32; // nbr prefetch words
    const long long NWS = ((long long)in_sizes[6]) / 32;

    // ---- prologue: normalization constants (fp32 1-channel chain) ----
    k_zero_fronts<<<gridFor((Mbi + 1) + (Msp + 1)), B>>>(Mbi + 1, Msp + 1);
    k_splat1z<<<gridFor((long long)N * 9 + NBH + NSH + NWB + NWS), B>>>(
        ws_bi, os_bi, N * 6, ws_sp, os_sp, N * 3, 2, NBH, 2, NSH,
        nbr_bi, NWB, nbr_sp, NWS);
    int cb_ = 0, cs_ = 0;
    for (int j = 0; j < 6; j++) {
        int hassp = (j < 3);
        int bd = 1 - cb_;
        int sd = 1 - cs_;
        long long tot = (Mbi + 1) + (hassp ? (Msp + 1) : 0);
        k_blur1_both<<<gridFor(tot), B>>>(bd, cb_, nbr_bi + (long long)j * Mbi * 2, Mbi,
                                          sd, cs_, nbr_sp + (long long)j * Msp * 2, Msp, hassp);
        cb_ = bd;
        if (hassp) cs_ = sd;
    }
    // bi 1-ch final in buffer cb_ (=0), sp in cs_ (=1)

    // ---- initial Q = softmax(-u): computes norms inline, splats into bi2/sp2 ----
    k_update_splat<<<gridFor((long long)N * 4), B>>>(
        unary, out, ws_bi, os_bi, ws_sp, os_sp, N,
        /*usepair=*/0, /*to_ext=*/0, /*do_splat=*/1, /*do_norm=*/1,
        0, 0, /*wr_bi=*/2, /*wr_sp=*/2, CB, CS,
        cb_, cs_, ALPHA_BI, ALPHA_SP);

    // ---- mean-field iterations (triple-buffer rotation) ----
    int sB = 2, tB = 0, zB = 1;   // bi: splat-src / pong / to-zero
    int sS = 2, tS = 0, zS = 1;   // sp
    for (int it = 0; it < 5; it++) {
        int c = sB, csp = sS;
        for (int j = 0; j < 6; j++) {
            int hassp = (j < 3);
            int d   = (c   == sB) ? tB : sB;
            int dsp = (csp == sS) ? tS : sS;
            long long tot = NBH + (hassp ? NSH : 0) + ((j == 0) ? (NBH + NSH) : 0);
            if (j == 0) {
                k_blurHz<<<gridFor(tot), B>>>(d, c, nbr_bi + (long long)j * Mbi * 2, Mbi,
                                              dsp, csp, nbr_sp + (long long)j * Msp * 2, Msp,
                                              hassp, zB, NBH, zS, NSH);
            } else {
                k_blurHz<<<gridFor(tot), B>>>(d, c, nbr_bi + (long long)j * Mbi * 2, Mbi,
                                              dsp, csp, nbr_sp + (long long)j * Msp * 2, Msp,
                                              hassp, 0, 0, 0, 0);
            }
            c = d;
            if (hassp) csp = dsp;
        }
        // bi result in sB (6 flips), sp result in tS (3 flips)
        if (it < 4) {
            k_update_splat<<<gridFor((long long)N * 4), B>>>(
                unary, out, ws_bi, os_bi, ws_sp, os_sp, N,
                /*usepair=*/1, /*to_ext=*/0, /*do_splat=*/1, /*do_norm=*/0,
                sB, tS, /*wr_bi=*/zB, /*wr_sp=*/zS, CB, CS, 0, 0, 0.f, 0.f);
            int nB_ = zB; zB = sB; sB = nB_;                   // tB unchanged
            int nS_ = zS; zS = tS; tS = sS; sS = nS_;
        } else {
            k_update_splat<<<gridFor((long long)N * 4), B>>>(
                unary, out, ws_bi, os_bi, ws_sp, os_sp, N,
                /*usepair=*/1, /*to_ext=*/1, /*do_splat=*/0, /*do_norm=*/0,
                sB, tS, 0, 0, CB, CS, 0, 0, 0.f, 0.f);
        }
    }
}